// round 2
// baseline (speedup 1.0000x reference)
#include <cuda_runtime.h>

#define H      768
#define DD     192
#define WIN    960          // H + DD
#define NCOMBO (8 * 17)     // 8 tokens x (16 dinuc states + 1 zero-pad state)
#define SEQ    2048
#define LN_EPS 1e-12f

// Scratch (no cudaMalloc allowed)
__device__ float g_ytok[8 * H];        // token_emb @ W[:, :768]^T
__device__ float g_ydin[16 * H];       // dinuc_emb @ W[:, 768:960]^T
__device__ float g_table[NCOMBO * H];  // final layernormed rows
__device__ int   g_is64;               // 1 if input_ids is int64, 0 if int32

// ---------------------------------------------------------------------------
// Detect whether input_ids is int64 (little-endian: odd 32-bit words are the
// high halves and must be 0 since values are in [0,8)) or int32.
// Checks 64 token positions; random int32 data in [0,8) would need 64 zeros
// in a row to fool this (prob ~ 8^-64).
// ---------------------------------------------------------------------------
__global__ void detect_kernel(const int* __restrict__ ids32) {
    if (threadIdx.x == 0) {
        int ok = 1;
        #pragma unroll 8
        for (int i = 0; i < 64; i++) {
            if (ids32[2 * i + 1] != 0) ok = 0;
        }
        g_is64 = ok;
    }
}

// ---------------------------------------------------------------------------
// Kernel 1: tiny GEMVs. Blocks 0..7: y_tok[a] (len-768 dots).
//           Blocks 8..23: y_din[d]  (len-192 dots).
// ---------------------------------------------------------------------------
__global__ __launch_bounds__(H) void partial_kernel(
    const float* __restrict__ tok_emb,   // [8, 768]
    const float* __restrict__ din_emb,   // [16, 192]
    const float* __restrict__ W)         // [768, 960] row-major
{
    __shared__ float s_emb[H];
    const int o = threadIdx.x;     // output channel
    const int b = blockIdx.x;

    if (b < 8) {
        s_emb[o] = tok_emb[b * H + o];
        __syncthreads();
        const float4* w4 = reinterpret_cast<const float4*>(W + (size_t)o * WIN);
        const float4* e4 = reinterpret_cast<const float4*>(s_emb);
        float acc = 0.f;
        #pragma unroll 8
        for (int i = 0; i < H / 4; i++) {
            float4 w = w4[i], e = e4[i];
            acc += w.x * e.x + w.y * e.y + w.z * e.z + w.w * e.w;
        }
        g_ytok[b * H + o] = acc;
    } else {
        const int d = b - 8;
        if (o < DD) s_emb[o] = din_emb[d * DD + o];
        __syncthreads();
        const float4* w4 = reinterpret_cast<const float4*>(W + (size_t)o * WIN + H);
        const float4* e4 = reinterpret_cast<const float4*>(s_emb);
        float acc = 0.f;
        #pragma unroll 8
        for (int i = 0; i < DD / 4; i++) {
            float4 w = w4[i], e = e4[i];
            acc += w.x * e.x + w.y * e.y + w.z * e.z + w.w * e.w;
        }
        g_ydin[d * H + o] = acc;
    }
}

// ---------------------------------------------------------------------------
// Kernel 2: build the 136-row layernormed table.
//   combo = a*17 + d; d==16 means "zero dinuc" (last seq position padding).
//   Two-pass mean/var to match reference numerics.
// ---------------------------------------------------------------------------
__global__ __launch_bounds__(H) void table_kernel(
    const float* __restrict__ bias,
    const float* __restrict__ gamma,
    const float* __restrict__ beta)
{
    const int o    = threadIdx.x;
    const int a    = blockIdx.x / 17;
    const int d    = blockIdx.x % 17;
    const int lane = o & 31;
    const int warp = o >> 5;

    float x = g_ytok[a * H + o] + bias[o];
    if (d < 16) x += g_ydin[d * H + o];

    __shared__ float sred[32];
    __shared__ float s_mu, s_var;

    // pass 1: mean
    float v = x;
    #pragma unroll
    for (int off = 16; off > 0; off >>= 1) v += __shfl_down_sync(0xffffffffu, v, off);
    if (lane == 0) sred[warp] = v;
    __syncthreads();
    if (o < 32) {
        float t = (o < (H / 32)) ? sred[o] : 0.f;
        #pragma unroll
        for (int off = 16; off > 0; off >>= 1) t += __shfl_down_sync(0xffffffffu, t, off);
        if (o == 0) s_mu = t * (1.0f / H);
    }
    __syncthreads();

    // pass 2: variance of (x - mu)
    const float dx = x - s_mu;
    v = dx * dx;
    #pragma unroll
    for (int off = 16; off > 0; off >>= 1) v += __shfl_down_sync(0xffffffffu, v, off);
    if (lane == 0) sred[warp] = v;
    __syncthreads();
    if (o < 32) {
        float t = (o < (H / 32)) ? sred[o] : 0.f;
        #pragma unroll
        for (int off = 16; off > 0; off >>= 1) t += __shfl_down_sync(0xffffffffu, t, off);
        if (o == 0) s_var = t * (1.0f / H);
    }
    __syncthreads();

    const float inv = rsqrtf(s_var + LN_EPS);
    g_table[blockIdx.x * H + o] = dx * inv * gamma[o] + beta[o];
}

// ---------------------------------------------------------------------------
// Kernel 3: gather. One block per token, 192 threads copy 768 floats (float4).
// Streaming stores keep the hot table + ids in cache.
// ---------------------------------------------------------------------------
__global__ __launch_bounds__(192) void gather_kernel(
    const int* __restrict__ ids32,     // raw words; stride depends on g_is64
    float* __restrict__ out)
{
    const int t      = blockIdx.x;
    const int s      = t & (SEQ - 1);
    const int stride = g_is64 ? 2 : 1;    // int64 -> low word at 2*t

    const int a = __ldg(&ids32[t * stride]);
    int combo;
    if (s == SEQ - 1) {
        combo = a * 17 + 16;              // zero-pad dinuc state
    } else {
        const int nx = __ldg(&ids32[(t + 1) * stride]);
        const int dd = (a >= 4 && nx >= 4) ? ((a - 4) * 4 + (nx - 4)) : 0;
        combo = a * 17 + dd;
    }

    const float4* src = reinterpret_cast<const float4*>(g_table) + combo * (H / 4);
    float4*       dst = reinterpret_cast<float4*>(out) + (size_t)t * (H / 4);
    __stcs(&dst[threadIdx.x], src[threadIdx.x]);
}

// ---------------------------------------------------------------------------
extern "C" void kernel_launch(void* const* d_in, const int* in_sizes, int n_in,
                              void* d_out, int out_size) {
    const int*   ids32   = (const int*)d_in[0];   // int32 or int64 raw words
    const float* tok_emb = (const float*)d_in[1];
    const float* din_emb = (const float*)d_in[2];
    const float* W       = (const float*)d_in[3];
    const float* bias    = (const float*)d_in[4];
    const float* gamma   = (const float*)d_in[5];
    const float* beta    = (const float*)d_in[6];
    float*       out     = (float*)d_out;

    const int n_tokens = in_sizes[0];             // 32 * 2048 = 65536

    detect_kernel<<<1, 32>>>(ids32);
    partial_kernel<<<24, H>>>(tok_emb, din_emb, W);
    table_kernel<<<NCOMBO, H>>>(bias, gamma, beta);
    gather_kernel<<<n_tokens, 192>>>(ids32, out);
}

// round 3
// speedup vs baseline: 2.7036x; 2.7036x over previous
#include <cuda_runtime.h>

#define H      768
#define DD     192
#define WIN    960          // H + DD
#define NCOMBO (8 * 17)     // 8 tokens x (16 dinuc states + 1 zero-pad state)
#define SEQ    2048
#define LN_EPS 1e-12f
#define TOK_PER_BLK 16

// Scratch (no cudaMalloc allowed)
__device__ float g_ytok[8 * H];        // token_emb @ W[:, :768]^T
__device__ float g_ydin[16 * H];       // dinuc_emb @ W[:, 768:960]^T
__device__ float g_table[NCOMBO * H];  // final layernormed rows
__device__ int   g_is64;               // 1 if input_ids is int64, 0 if int32

// ---------------------------------------------------------------------------
// Kernel 1: warp-per-output-channel GEMV. 96 blocks x 256 threads (8 warps).
// Warp w of block b owns channel o = b*8+w, streams W[o][:] coalesced and
// reuses each element across all 8 token rows + 16 dinuc rows (in shared).
// Block 0 / thread 0 also runs the int64-vs-int32 sniffer (odd 32-bit words
// of little-endian int64 values in [0,8) must all be zero; 64 samples).
// ---------------------------------------------------------------------------
__global__ __launch_bounds__(256) void partial_kernel(
    const int*   __restrict__ ids32,
    const float* __restrict__ tok_emb,   // [8, 768]
    const float* __restrict__ din_emb,   // [16, 192]
    const float* __restrict__ W)         // [768, 960] row-major
{
    __shared__ float s_tok[8 * H];    // 24 KB
    __shared__ float s_din[16 * DD];  // 12 KB

    const int tid  = threadIdx.x;
    const int lane = tid & 31;
    const int warp = tid >> 5;
    const int o    = blockIdx.x * 8 + warp;

    if (blockIdx.x == 0 && tid == 0) {
        int ok = 1;
        #pragma unroll 8
        for (int i = 0; i < 64; i++)
            if (ids32[2 * i + 1] != 0) ok = 0;
        g_is64 = ok;
    }

    for (int i = tid; i < 8 * H; i += 256)   s_tok[i] = tok_emb[i];
    for (int i = tid; i < 16 * DD; i += 256) s_din[i] = din_emb[i];
    __syncthreads();

    const float* Wo = W + (size_t)o * WIN;

    // --- token part: 8 simultaneous dots of length 768 ---
    float acc[8];
    #pragma unroll
    for (int a = 0; a < 8; a++) acc[a] = 0.f;

    for (int i = lane; i < H; i += 32) {
        const float wv = Wo[i];
        #pragma unroll
        for (int a = 0; a < 8; a++) acc[a] += wv * s_tok[a * H + i];
    }
    #pragma unroll
    for (int a = 0; a < 8; a++) {
        float v = acc[a];
        #pragma unroll
        for (int off = 16; off > 0; off >>= 1) v += __shfl_down_sync(0xffffffffu, v, off);
        if (lane == 0) g_ytok[a * H + o] = v;
    }

    // --- dinuc part: 16 simultaneous dots of length 192 ---
    float accd[16];
    #pragma unroll
    for (int d = 0; d < 16; d++) accd[d] = 0.f;

    for (int i = lane; i < DD; i += 32) {
        const float wv = Wo[H + i];
        #pragma unroll
        for (int d = 0; d < 16; d++) accd[d] += wv * s_din[d * DD + i];
    }
    #pragma unroll
    for (int d = 0; d < 16; d++) {
        float v = accd[d];
        #pragma unroll
        for (int off = 16; off > 0; off >>= 1) v += __shfl_down_sync(0xffffffffu, v, off);
        if (lane == 0) g_ydin[d * H + o] = v;
    }
}

// ---------------------------------------------------------------------------
// Kernel 2: build the 136-row layernormed table (two-pass mean/var).
// ---------------------------------------------------------------------------
__global__ __launch_bounds__(H) void table_kernel(
    const float* __restrict__ bias,
    const float* __restrict__ gamma,
    const float* __restrict__ beta)
{
    const int o    = threadIdx.x;
    const int a    = blockIdx.x / 17;
    const int d    = blockIdx.x % 17;
    const int lane = o & 31;
    const int warp = o >> 5;

    float x = g_ytok[a * H + o] + bias[o];
    if (d < 16) x += g_ydin[d * H + o];

    __shared__ float sred[32];
    __shared__ float s_mu, s_var;

    float v = x;
    #pragma unroll
    for (int off = 16; off > 0; off >>= 1) v += __shfl_down_sync(0xffffffffu, v, off);
    if (lane == 0) sred[warp] = v;
    __syncthreads();
    if (o < 32) {
        float t = (o < (H / 32)) ? sred[o] : 0.f;
        #pragma unroll
        for (int off = 16; off > 0; off >>= 1) t += __shfl_down_sync(0xffffffffu, t, off);
        if (o == 0) s_mu = t * (1.0f / H);
    }
    __syncthreads();

    const float dx = x - s_mu;
    v = dx * dx;
    #pragma unroll
    for (int off = 16; off > 0; off >>= 1) v += __shfl_down_sync(0xffffffffu, v, off);
    if (lane == 0) sred[warp] = v;
    __syncthreads();
    if (o < 32) {
        float t = (o < (H / 32)) ? sred[o] : 0.f;
        #pragma unroll
        for (int off = 16; off > 0; off >>= 1) t += __shfl_down_sync(0xffffffffu, t, off);
        if (o == 0) s_var = t * (1.0f / H);
    }
    __syncthreads();

    const float inv = rsqrtf(s_var + LN_EPS);
    g_table[blockIdx.x * H + o] = dx * inv * gamma[o] + beta[o];
}

// ---------------------------------------------------------------------------
// Kernel 3: gather. 16 tokens per block, 192 threads. Combos precomputed to
// shared, then an unrolled copy loop gives 16-deep load/store MLP per thread.
// ---------------------------------------------------------------------------
__global__ __launch_bounds__(192) void gather_kernel(
    const int* __restrict__ ids32,     // raw words; stride depends on g_is64
    float* __restrict__ out,
    int n_tokens)
{
    __shared__ int s_combo[TOK_PER_BLK];

    const int tid   = threadIdx.x;
    const int tbase = blockIdx.x * TOK_PER_BLK;

    if (tid < TOK_PER_BLK) {
        const int t = tbase + tid;
        int combo = 0;
        if (t < n_tokens) {
            const int stride = g_is64 ? 2 : 1;
            const int a = __ldg(&ids32[t * stride]);
            const int s = t & (SEQ - 1);
            if (s == SEQ - 1) {
                combo = a * 17 + 16;          // zero-pad dinuc state
            } else {
                const int nx = __ldg(&ids32[(t + 1) * stride]);
                const int dd = (a >= 4 && nx >= 4) ? ((a - 4) * 4 + (nx - 4)) : 0;
                combo = a * 17 + dd;
            }
        }
        s_combo[tid] = combo;
    }
    __syncthreads();

    const float4* tab4 = reinterpret_cast<const float4*>(g_table);
    float4*       out4 = reinterpret_cast<float4*>(out) + (size_t)tbase * (H / 4) + tid;

    #pragma unroll
    for (int i = 0; i < TOK_PER_BLK; i++) {
        const float4 v = __ldg(&tab4[s_combo[i] * (H / 4) + tid]);
        __stcs(out4, v);
        out4 += (H / 4);
    }
}

// ---------------------------------------------------------------------------
extern "C" void kernel_launch(void* const* d_in, const int* in_sizes, int n_in,
                              void* d_out, int out_size) {
    const int*   ids32   = (const int*)d_in[0];
    const float* tok_emb = (const float*)d_in[1];
    const float* din_emb = (const float*)d_in[2];
    const float* W       = (const float*)d_in[3];
    const float* bias    = (const float*)d_in[4];
    const float* gamma   = (const float*)d_in[5];
    const float* beta    = (const float*)d_in[6];
    float*       out     = (float*)d_out;

    const int n_tokens = in_sizes[0];                     // 65536
    const int nblk     = (n_tokens + TOK_PER_BLK - 1) / TOK_PER_BLK;

    partial_kernel<<<96, 256>>>(ids32, tok_emb, din_emb, W);
    table_kernel<<<NCOMBO, H>>>(bias, gamma, beta);
    gather_kernel<<<nblk, 192>>>(ids32, out, n_tokens);
}

// round 4
// speedup vs baseline: 2.9756x; 1.1006x over previous
#include <cuda_runtime.h>

#define H      768
#define DD     192
#define WIN    960          // H + DD
#define NCOMBO (8 * 17)     // 8 tokens x (16 dinuc states + 1 zero-pad state)
#define SEQ    2048
#define LN_EPS 1e-12f
#define TOK_PER_BLK 16

// Scratch (no cudaMalloc allowed)
__device__ float g_ytok[8 * H];        // token_emb @ W[:, :768]^T
__device__ float g_ydin[16 * H];       // dinuc_emb @ W[:, 768:960]^T
__device__ float g_table[NCOMBO * H];  // final layernormed rows
__device__ int   g_is64;               // 1 if input_ids is int64, 0 if int32

// ---------------------------------------------------------------------------
// Kernel 1: warp-per-output-channel GEMV, MLP-maximized.
// 96 blocks x 256 threads (8 warps). Warp w of block b owns channel o=b*8+w.
// The warp's full W row (768 floats) is loaded as 6 independent float4 per
// lane UP FRONT (MLP=8 incl. dinuc slice), then FMAs run from shared (LDS.128).
// Block 0 / thread 0 also runs the int64-vs-int32 sniffer.
// ---------------------------------------------------------------------------
__global__ __launch_bounds__(256) void partial_kernel(
    const int*   __restrict__ ids32,
    const float* __restrict__ tok_emb,   // [8, 768]
    const float* __restrict__ din_emb,   // [16, 192]
    const float* __restrict__ W)         // [768, 960] row-major
{
    __shared__ float s_tok[8 * H];    // 24 KB
    __shared__ float s_din[16 * DD];  // 12 KB

    const int tid  = threadIdx.x;
    const int lane = tid & 31;
    const int warp = tid >> 5;
    const int o    = blockIdx.x * 8 + warp;

    if (blockIdx.x == 0 && tid == 0) {
        int ok = 1;
        #pragma unroll 8
        for (int i = 0; i < 64; i++)
            if (ids32[2 * i + 1] != 0) ok = 0;
        g_is64 = ok;
    }

    // ---- front-batched W loads: 6 (token) + 2 (dinuc) independent float4 ----
    const float4* Wo4 = reinterpret_cast<const float4*>(W + (size_t)o * WIN);
    float4 wt[6];
    #pragma unroll
    for (int p = 0; p < 6; p++) wt[p] = __ldg(&Wo4[p * 32 + lane]);

    const float4* Wd4 = reinterpret_cast<const float4*>(W + (size_t)o * WIN + H);
    float4 wd0, wd1;
    wd0 = __ldg(&Wd4[lane]);
    wd1 = (lane < 16) ? __ldg(&Wd4[32 + lane]) : make_float4(0.f, 0.f, 0.f, 0.f);

    // ---- stage embeddings to shared (float4 fills, 9 loads/thread) ----
    {
        const float4* te4 = reinterpret_cast<const float4*>(tok_emb);
        float4* st4 = reinterpret_cast<float4*>(s_tok);
        #pragma unroll
        for (int i = 0; i < 6; i++) st4[i * 256 + tid] = __ldg(&te4[i * 256 + tid]);
        const float4* de4 = reinterpret_cast<const float4*>(din_emb);
        float4* sd4 = reinterpret_cast<float4*>(s_din);
        #pragma unroll
        for (int i = 0; i < 3; i++) sd4[i * 256 + tid] = __ldg(&de4[i * 256 + tid]);
    }
    __syncthreads();

    // ---- token part: 8 dots of length 768, vectorized ----
    float acc[8];
    #pragma unroll
    for (int a = 0; a < 8; a++) acc[a] = 0.f;

    #pragma unroll
    for (int p = 0; p < 6; p++) {
        const int base = (p * 32 + lane) * 4;
        #pragma unroll
        for (int a = 0; a < 8; a++) {
            const float4 e = *reinterpret_cast<const float4*>(&s_tok[a * H + base]);
            acc[a] += wt[p].x * e.x + wt[p].y * e.y + wt[p].z * e.z + wt[p].w * e.w;
        }
    }
    #pragma unroll
    for (int a = 0; a < 8; a++) {
        float v = acc[a];
        #pragma unroll
        for (int off = 16; off > 0; off >>= 1) v += __shfl_down_sync(0xffffffffu, v, off);
        if (lane == 0) g_ytok[a * H + o] = v;
    }

    // ---- dinuc part: 16 dots of length 192, vectorized ----
    float accd[16];
    #pragma unroll
    for (int d = 0; d < 16; d++) accd[d] = 0.f;

    {
        const int base0 = lane * 4;
        #pragma unroll
        for (int d = 0; d < 16; d++) {
            const float4 e = *reinterpret_cast<const float4*>(&s_din[d * DD + base0]);
            accd[d] += wd0.x * e.x + wd0.y * e.y + wd0.z * e.z + wd0.w * e.w;
        }
        if (lane < 16) {
            const int base1 = (32 + lane) * 4;
            #pragma unroll
            for (int d = 0; d < 16; d++) {
                const float4 e = *reinterpret_cast<const float4*>(&s_din[d * DD + base1]);
                accd[d] += wd1.x * e.x + wd1.y * e.y + wd1.z * e.z + wd1.w * e.w;
            }
        }
    }
    #pragma unroll
    for (int d = 0; d < 16; d++) {
        float v = accd[d];
        #pragma unroll
        for (int off = 16; off > 0; off >>= 1) v += __shfl_down_sync(0xffffffffu, v, off);
        if (lane == 0) g_ydin[d * H + o] = v;
    }
}

// ---------------------------------------------------------------------------
// Kernel 2: build the 136-row layernormed table (two-pass mean/var).
// ---------------------------------------------------------------------------
__global__ __launch_bounds__(H) void table_kernel(
    const float* __restrict__ bias,
    const float* __restrict__ gamma,
    const float* __restrict__ beta)
{
    const int o    = threadIdx.x;
    const int a    = blockIdx.x / 17;
    const int d    = blockIdx.x % 17;
    const int lane = o & 31;
    const int warp = o >> 5;

    float x = g_ytok[a * H + o] + bias[o];
    if (d < 16) x += g_ydin[d * H + o];

    __shared__ float sred[32];
    __shared__ float s_mu, s_var;

    float v = x;
    #pragma unroll
    for (int off = 16; off > 0; off >>= 1) v += __shfl_down_sync(0xffffffffu, v, off);
    if (lane == 0) sred[warp] = v;
    __syncthreads();
    if (o < 32) {
        float t = (o < (H / 32)) ? sred[o] : 0.f;
        #pragma unroll
        for (int off = 16; off > 0; off >>= 1) t += __shfl_down_sync(0xffffffffu, t, off);
        if (o == 0) s_mu = t * (1.0f / H);
    }
    __syncthreads();

    const float dx = x - s_mu;
    v = dx * dx;
    #pragma unroll
    for (int off = 16; off > 0; off >>= 1) v += __shfl_down_sync(0xffffffffu, v, off);
    if (lane == 0) sred[warp] = v;
    __syncthreads();
    if (o < 32) {
        float t = (o < (H / 32)) ? sred[o] : 0.f;
        #pragma unroll
        for (int off = 16; off > 0; off >>= 1) t += __shfl_down_sync(0xffffffffu, t, off);
        if (o == 0) s_var = t * (1.0f / H);
    }
    __syncthreads();

    const float inv = rsqrtf(s_var + LN_EPS);
    g_table[blockIdx.x * H + o] = dx * inv * gamma[o] + beta[o];
}

// ---------------------------------------------------------------------------
// Kernel 3: gather. 16 tokens per block, 192 threads. Combos precomputed to
// shared, then an unrolled copy loop gives 16-deep load/store MLP per thread.
// ---------------------------------------------------------------------------
__global__ __launch_bounds__(192) void gather_kernel(
    const int* __restrict__ ids32,     // raw words; stride depends on g_is64
    float* __restrict__ out,
    int n_tokens)
{
    __shared__ int s_combo[TOK_PER_BLK];

    const int tid   = threadIdx.x;
    const int tbase = blockIdx.x * TOK_PER_BLK;

    if (tid < TOK_PER_BLK) {
        const int t = tbase + tid;
        int combo = 0;
        if (t < n_tokens) {
            const int stride = g_is64 ? 2 : 1;
            const int a = __ldg(&ids32[t * stride]);
            const int s = t & (SEQ - 1);
            if (s == SEQ - 1) {
                combo = a * 17 + 16;          // zero-pad dinuc state
            } else {
                const int nx = __ldg(&ids32[(t + 1) * stride]);
                const int dd = (a >= 4 && nx >= 4) ? ((a - 4) * 4 + (nx - 4)) : 0;
                combo = a * 17 + dd;
            }
        }
        s_combo[tid] = combo;
    }
    __syncthreads();

    const float4* tab4 = reinterpret_cast<const float4*>(g_table);
    float4*       out4 = reinterpret_cast<float4*>(out) + (size_t)tbase * (H / 4) + tid;

    #pragma unroll
    for (int i = 0; i < TOK_PER_BLK; i++) {
        const float4 v = __ldg(&tab4[s_combo[i] * (H / 4) + tid]);
        __stcs(out4, v);
        out4 += (H / 4);
    }
}

// ---------------------------------------------------------------------------
extern "C" void kernel_launch(void* const* d_in, const int* in_sizes, int n_in,
                              void* d_out, int out_size) {
    const int*   ids32   = (const int*)d_in[0];
    const float* tok_emb = (const float*)d_in[1];
    const float* din_emb = (const float*)d_in[2];
    const float* W       = (const float*)d_in[3];
    const float* bias    = (const float*)d_in[4];
    const float* gamma   = (const float*)d_in[5];
    const float* beta    = (const float*)d_in[6];
    float*       out     = (float*)d_out;

    const int n_tokens = in_sizes[0];                     // 65536
    const int nblk     = (n_tokens + TOK_PER_BLK - 1) / TOK_PER_BLK;

    partial_kernel<<<96, 256>>>(ids32, tok_emb, din_emb, W);
    table_kernel<<<NCOMBO, H>>>(bias, gamma, beta);
    gather_kernel<<<nblk, 192>>>(ids32, out, n_tokens);
}